// round 13
// baseline (speedup 1.0000x reference)
#include <cuda_runtime.h>
#include <math.h>

#define NN    50000
#define EE    800000
#define TT    32
#define CH    64          // CHUNK = CIN/T
#define HH    96
#define CIN   2048
#define EPS_BN 1e-5f
#define VTH    0.005f

typedef unsigned long long u64;

// packed dual-fp32 FMA: d.lo = a.lo*b.lo + c.lo ; d.hi = a.hi*b.hi + c.hi
__device__ __forceinline__ u64 ffma2(u64 a, u64 b, u64 c) {
    u64 d;
    asm("fma.rn.f32x2 %0, %1, %2, %3;" : "=l"(d) : "l"(a), "l"(b), "l"(c));
    return d;
}
__device__ __forceinline__ float2 unpack2(u64 v) {
    float2 f;
    asm("mov.b64 {%0, %1}, %2;" : "=f"(f.x), "=f"(f.y) : "l"(v));
    return f;
}

// ---------------- persistent device scratch (no allocation allowed) -------
__device__ int   g_deg[NN];
__device__ int   g_cnt[NN];
__device__ int   g_off[NN + 1];
__device__ int2  g_epack[EE];           // {src, weight bits}
__device__ float g_dinv[NN];
__device__ float g_snorm[NN];
__device__ float g_rsum[NN];
__device__ float g_ss[HH];              // shared-BN scale
__device__ float g_cs[HH];              // shared-BN shift
__device__ float g_lwsum[HH];           // sum(lin_w, axis=0)
__device__ float g_s1[TT * CH];         // input-BN scale, all steps
__device__ float g_c1[TT * CH];         // input-BN shift, all steps
__device__ float g_h2all[(size_t)TT * NN * HH];   // bns(elu(gcn1)) for all t
__device__ float g_dvall[(size_t)TT * NN * HH];   // gcn2 output (dv) for all t

// ---------------- preprocessing (exactly 5 launches) ----------------------
__global__ void k_pre0(const float* __restrict__ bg, const float* __restrict__ bb,
                       const float* __restrict__ bm, const float* __restrict__ bv,
                       const float* __restrict__ lw,
                       const float* __restrict__ g1, const float* __restrict__ b1,
                       const float* __restrict__ m1, const float* __restrict__ v1) {
    int i = blockIdx.x * blockDim.x + threadIdx.x;
    if (i < NN) { g_deg[i] = 0; g_cnt[i] = 0; }   // MUST reset every call
    if (i < TT * CH) {
        float s = g1[i] * rsqrtf(v1[i] + EPS_BN);
        g_s1[i] = s;
        g_c1[i] = b1[i] - m1[i] * s;
    }
    if (i < HH) {
        float s = bg[i] * rsqrtf(bv[i] + EPS_BN);
        g_ss[i] = s;
        g_cs[i] = bb[i] - bm[i] * s;
        float acc = 0.f;
        for (int o = 0; o < HH; o++) acc += lw[o * HH + i];
        g_lwsum[i] = acc;
    }
}

__global__ void k_deg(const int* __restrict__ ei) {
    int e = blockIdx.x * blockDim.x + threadIdx.x;
    if (e < EE) atomicAdd(&g_deg[ei[EE + e]], 1);
}

__global__ void k_scan_dinv() {
    __shared__ int buf[1024];
    __shared__ int carry;
    int tid = threadIdx.x;
    if (tid == 0) carry = 0;
    __syncthreads();
    for (int base = 0; base < NN; base += 1024) {
        int i = base + tid;
        int val = 0;
        if (i < NN) {
            val = g_deg[i];
            float d = (float)(val + 1);
            g_dinv[i]  = rsqrtf(d);
            g_snorm[i] = 1.0f / d;
        }
        buf[tid] = val;
        __syncthreads();
        for (int off = 1; off < 1024; off <<= 1) {
            int t2 = (tid >= off) ? buf[tid - off] : 0;
            __syncthreads();
            buf[tid] += t2;
            __syncthreads();
        }
        if (i < NN) g_off[i] = carry + buf[tid] - val;   // exclusive
        __syncthreads();
        if (tid == 0) carry += buf[1023];
        __syncthreads();
    }
    if (tid == 0) g_off[NN] = carry;
}

__global__ void k_fill(const int* __restrict__ ei) {
    int e = blockIdx.x * blockDim.x + threadIdx.x;
    if (e < EE) {
        int s = ei[e];
        int d = ei[EE + e];
        int pos = g_off[d] + atomicAdd(&g_cnt[d], 1);
        g_epack[pos] = make_int2(s, __float_as_int(g_dinv[s] * g_dinv[d]));
    }
}

__global__ void k_rsum() {
    int n = blockIdx.x * blockDim.x + threadIdx.x;
    if (n < NN) {
        float r = g_snorm[n];
        int e1 = g_off[n + 1];
        for (int e = g_off[n]; e < e1; e++) r += __int_as_float(g_epack[e].y);
        g_rsum[n] = r;
    }
}

// ---------------- fused kernel 1 (ALL t in one launch) --------------------
// block (bx, t): agg(x chunk t)+BN fold -> GEMM1(64->96, FFMA2) -> elu -> bns
// dyn smem: a_s[64*68] floats | w_d[64*96] float2 (duplicated)
#define SMEM1_BYTES (CH * 68 * 4 + CH * HH * 8)
__global__ __launch_bounds__(384) void k_fused1(
    const float* __restrict__ x, const float* __restrict__ w1,
    const float* __restrict__ b1)
{
    extern __shared__ float dsm[];
    float*  a_s = dsm;                         // [64][68]
    float2* w_d = (float2*)(dsm + CH * 68);    // [64][96] dup pairs

    int t    = blockIdx.y;
    int tid  = threadIdx.x;
    int warp = tid >> 5;
    int lane = tid & 31;
    int m0   = blockIdx.x * 64;

    const float* wt = w1 + t * CH * HH;
    for (int idx = tid; idx < CH * HH; idx += 384) {
        float v = wt[idx];
        w_d[idx] = make_float2(v, v);
    }

    // fused aggregation: lane handles channels 2*lane, 2*lane+1 (float2)
    const float* s1 = g_s1 + t * CH;
    const float* c1 = g_c1 + t * CH;
    float s1a = s1[2 * lane], s1b = s1[2 * lane + 1];
    float c1a = c1[2 * lane], c1b = c1[2 * lane + 1];
    for (int m = warp; m < 64; m += 12) {
        int n = m0 + m;
        if (n >= NN) { a_s[(2 * lane) * 68 + m] = 0.f; a_s[(2 * lane + 1) * 68 + m] = 0.f; continue; }
        const float2* xb = (const float2*)(x + (size_t)n * CIN + t * CH);
        float sn = g_snorm[n];
        float2 xv = xb[lane];
        float a0 = sn * xv.x;
        float a1 = sn * xv.y;
        int e0 = g_off[n], e1 = g_off[n + 1];
#pragma unroll 4
        for (int e = e0; e < e1; e++) {
            int2  p = g_epack[e];
            float w = __int_as_float(p.y);
            float2 v = ((const float2*)(x + (size_t)p.x * CIN + t * CH))[lane];
            a0 += w * v.x;
            a1 += w * v.y;
        }
        float r = g_rsum[n];
        a_s[(2 * lane) * 68 + m]     = a0 * s1a + r * c1a;
        a_s[(2 * lane + 1) * 68 + m] = a1 * s1b + r * c1b;
    }
    __syncthreads();

    int mt = (tid & 15) * 4;   // 0..60
    int jt = (tid >> 4) * 4;   // 0..92
    u64 acc2[2][4] = {};       // [m-pair][j]
#pragma unroll 8
    for (int k = 0; k < CH; k++) {
        ulonglong2 ap = *(const ulonglong2*)&a_s[k * 68 + mt];          // (m0,m1),(m2,m3)
        const ulonglong2* wp = (const ulonglong2*)&w_d[k * HH + jt];
        ulonglong2 w01 = wp[0];                                         // (j0,j0),(j1,j1)
        ulonglong2 w23 = wp[1];                                         // (j2,j2),(j3,j3)
        acc2[0][0] = ffma2(ap.x, w01.x, acc2[0][0]);
        acc2[1][0] = ffma2(ap.y, w01.x, acc2[1][0]);
        acc2[0][1] = ffma2(ap.x, w01.y, acc2[0][1]);
        acc2[1][1] = ffma2(ap.y, w01.y, acc2[1][1]);
        acc2[0][2] = ffma2(ap.x, w23.x, acc2[0][2]);
        acc2[1][2] = ffma2(ap.y, w23.x, acc2[1][2]);
        acc2[0][3] = ffma2(ap.x, w23.y, acc2[0][3]);
        acc2[1][3] = ffma2(ap.y, w23.y, acc2[1][3]);
    }
    float accf[4][4];
#pragma unroll
    for (int p = 0; p < 2; p++)
#pragma unroll
        for (int j = 0; j < 4; j++) {
            float2 f = unpack2(acc2[p][j]);
            accf[2 * p][j]     = f.x;
            accf[2 * p + 1][j] = f.y;
        }

    const float* b1t = b1 + t * HH;
    float bj[4], ssj[4], csj[4];
#pragma unroll
    for (int j = 0; j < 4; j++) {
        bj[j]  = b1t[jt + j];
        ssj[j] = g_ss[jt + j];
        csj[j] = g_cs[jt + j];
    }
    float* h2 = g_h2all + (size_t)t * NN * HH;
#pragma unroll
    for (int i = 0; i < 4; i++) {
        int n = m0 + mt + i;
        if (n < NN) {
            float o[4];
#pragma unroll
            for (int j = 0; j < 4; j++) {
                float z = accf[i][j] + bj[j];
                z = (z > 0.f) ? z : expm1f(z);
                o[j] = z * ssj[j] + csj[j];
            }
            *(float4*)&h2[(size_t)n * HH + jt] = make_float4(o[0], o[1], o[2], o[3]);
        }
    }
}

// ---------------- fused kernel 2 (ALL t in one launch) --------------------
// block (bx, t): agg(h2all[t]) -> GEMM2(96->96, FFMA2)+b2 -> dvall[t]
// dyn smem: a_s[96*68] floats | w_d[96*96] float2 (duplicated)
#define SMEM2_BYTES (HH * 68 * 4 + HH * HH * 8)
__global__ __launch_bounds__(384) void k_fused2(
    const float* __restrict__ w2, const float* __restrict__ b2)
{
    extern __shared__ float dsm[];
    float*  a_s = dsm;                         // [96][68]
    float2* w_d = (float2*)(dsm + HH * 68);    // [96][96] dup pairs

    int t    = blockIdx.y;
    int tid  = threadIdx.x;
    int warp = tid >> 5;
    int lane = tid & 31;
    int m0   = blockIdx.x * 64;

    for (int idx = tid; idx < HH * HH; idx += 384) {
        float v = w2[idx];
        w_d[idx] = make_float2(v, v);
    }

    const float* h2 = g_h2all + (size_t)t * NN * HH;
    for (int m = warp; m < 64; m += 12) {
        int n = m0 + m;
        if (n >= NN) {
            a_s[(2 * lane) * 68 + m]     = 0.f;
            a_s[(2 * lane + 1) * 68 + m] = 0.f;
            a_s[(64 + lane) * 68 + m]    = 0.f;
            continue;
        }
        const float* hb = h2 + (size_t)n * HH;
        float sn = g_snorm[n];
        float2 hv = ((const float2*)hb)[lane];
        float a0 = sn * hv.x;
        float a1 = sn * hv.y;
        float a2 = sn * hb[64 + lane];
        int e0 = g_off[n], e1 = g_off[n + 1];
#pragma unroll 4
        for (int e = e0; e < e1; e++) {
            int2  p = g_epack[e];
            float w = __int_as_float(p.y);
            const float* hs = h2 + (size_t)p.x * HH;
            float2 v = ((const float2*)hs)[lane];
            a0 += w * v.x;
            a1 += w * v.y;
            a2 += w * hs[64 + lane];
        }
        a_s[(2 * lane) * 68 + m]     = a0;
        a_s[(2 * lane + 1) * 68 + m] = a1;
        a_s[(64 + lane) * 68 + m]    = a2;
    }
    __syncthreads();

    int mt = (tid & 15) * 4;
    int jt = (tid >> 4) * 4;
    u64 acc2[2][4] = {};
#pragma unroll 8
    for (int k = 0; k < HH; k++) {
        ulonglong2 ap = *(const ulonglong2*)&a_s[k * 68 + mt];
        const ulonglong2* wp = (const ulonglong2*)&w_d[k * HH + jt];
        ulonglong2 w01 = wp[0];
        ulonglong2 w23 = wp[1];
        acc2[0][0] = ffma2(ap.x, w01.x, acc2[0][0]);
        acc2[1][0] = ffma2(ap.y, w01.x, acc2[1][0]);
        acc2[0][1] = ffma2(ap.x, w01.y, acc2[0][1]);
        acc2[1][1] = ffma2(ap.y, w01.y, acc2[1][1]);
        acc2[0][2] = ffma2(ap.x, w23.x, acc2[0][2]);
        acc2[1][2] = ffma2(ap.y, w23.x, acc2[1][2]);
        acc2[0][3] = ffma2(ap.x, w23.y, acc2[0][3]);
        acc2[1][3] = ffma2(ap.y, w23.y, acc2[1][3]);
    }
    float accf[4][4];
#pragma unroll
    for (int p = 0; p < 2; p++)
#pragma unroll
        for (int j = 0; j < 4; j++) {
            float2 f = unpack2(acc2[p][j]);
            accf[2 * p][j]     = f.x;
            accf[2 * p + 1][j] = f.y;
        }

    float bj[4];
#pragma unroll
    for (int j = 0; j < 4; j++) bj[j] = b2[jt + j];

    float* dv = g_dvall + (size_t)t * NN * HH;
#pragma unroll
    for (int i = 0; i < 4; i++) {
        int n = m0 + mt + i;
        if (n < NN) {
            *(float4*)&dv[(size_t)n * HH + jt] =
                make_float4(accf[i][0] + bj[0], accf[i][1] + bj[1],
                            accf[i][2] + bj[2], accf[i][3] + bj[3]);
        }
    }
}

// ---------------- PLIF scan: one warp per node, loop over t ---------------
__global__ __launch_bounds__(256) void k_plif(const float* __restrict__ tau,
                                              float* __restrict__ out)
{
    int gw   = (blockIdx.x * blockDim.x + threadIdx.x) >> 5;
    int lane = threadIdx.x & 31;
    if (gw >= NN) return;

    float l0 = g_lwsum[lane];
    float l1 = g_lwsum[lane + 32];
    float l2 = g_lwsum[lane + 64];
    float tauv = *tau;
    float rtau = 1.0f / tauv;

    float v0 = 0.f, v1 = 0.f, v2 = 0.f;
    size_t base = (size_t)gw * HH;
#pragma unroll 4
    for (int t = 0; t < TT; t++) {
        const float* dvp = g_dvall + (size_t)t * NN * HH + base;
        float d0 = dvp[lane];
        float d1 = dvp[lane + 32];
        float d2 = dvp[lane + 64];
        float n0 = v0 + (d0 - v0) * rtau;
        float n1 = v1 + (d1 - v1) * rtau;
        float n2 = v2 + (d2 - v2) * rtau;
        bool s0 = (n0 - VTH) > 0.f;
        bool s1 = (n1 - VTH) > 0.f;
        bool s2 = (n2 - VTH) > 0.f;
        v0 = s0 ? 0.f : n0;
        v1 = s1 ? 0.f : n1;
        v2 = s2 ? 0.f : n2;
        float pl = (s0 ? l0 : 0.f) + (s1 ? l1 : 0.f) + (s2 ? l2 : 0.f);
#pragma unroll
        for (int off = 16; off > 0; off >>= 1)
            pl += __shfl_down_sync(0xffffffff, pl, off);
        if (lane == 0) out[t * NN + gw] = pl;
    }
}

// ---------------- launch --------------------------------------------------
extern "C" void kernel_launch(void* const* d_in, const int* in_sizes, int n_in,
                              void* d_out, int out_size) {
    const float* x      = (const float*)d_in[0];
    const int*   ei     = (const int*)  d_in[1];
    const float* w1     = (const float*)d_in[2];
    const float* b1     = (const float*)d_in[3];
    const float* bn1_g  = (const float*)d_in[4];
    const float* bn1_b  = (const float*)d_in[5];
    const float* bn1_m  = (const float*)d_in[6];
    const float* bn1_v  = (const float*)d_in[7];
    const float* bns_g  = (const float*)d_in[8];
    const float* bns_b  = (const float*)d_in[9];
    const float* bns_m  = (const float*)d_in[10];
    const float* bns_v  = (const float*)d_in[11];
    const float* w2     = (const float*)d_in[12];
    const float* b2     = (const float*)d_in[13];
    const float* lin_w  = (const float*)d_in[14];
    const float* tau    = (const float*)d_in[15];
    float* out = (float*)d_out;

    static bool attr_set = false;
    if (!attr_set) {
        cudaFuncSetAttribute(k_fused1, cudaFuncAttributeMaxDynamicSharedMemorySize, SMEM1_BYTES);
        cudaFuncSetAttribute(k_fused2, cudaFuncAttributeMaxDynamicSharedMemorySize, SMEM2_BYTES);
        attr_set = true;
    }

    // exactly 5 preprocessing launches (grid covers NN for state reset!)
    k_pre0<<<(NN + 255) / 256, 256>>>(bns_g, bns_b, bns_m, bns_v, lin_w,
                                      bn1_g, bn1_b, bn1_m, bn1_v);
    k_deg<<<(EE + 255) / 256, 256>>>(ei);
    k_scan_dinv<<<1, 1024>>>();
    k_fill<<<(EE + 255) / 256, 256>>>(ei);
    k_rsum<<<(NN + 255) / 256, 256>>>();

    // 3 dense hot-loop launches
    int nb = (NN + 63) / 64;             // 782 node tiles
    dim3 grid(nb, TT);
    k_fused1<<<grid, 384, SMEM1_BYTES>>>(x, w1, b1);
    k_fused2<<<grid, 384, SMEM2_BYTES>>>(w2, b2);
    k_plif<<<(NN * 32 + 255) / 256, 256>>>(tau, out);
}

// round 15
// speedup vs baseline: 1.1951x; 1.1951x over previous
#include <cuda_runtime.h>
#include <math.h>

#define NN    50000
#define EE    800000
#define TT    32
#define CH    64          // CHUNK = CIN/T
#define HH    96
#define CIN   2048
#define EPS_BN 1e-5f
#define VTH    0.005f
#define NB    782        // ceil(NN/64) node tiles

// ---------------- persistent device scratch (no allocation allowed) -------
__device__ int   g_deg[NN];
__device__ int   g_cnt[NN];
__device__ int   g_off[NN + 1];
__device__ int2  g_epack[EE];           // {src, weight bits}
__device__ float g_dinv[NN];
__device__ float g_snorm[NN];
__device__ float g_rsum[NN];
__device__ float g_ss[HH];              // shared-BN scale
__device__ float g_cs[HH];              // shared-BN shift
__device__ float g_lwsum[HH];           // sum(lin_w, axis=0)
__device__ float g_s1[TT * CH];         // input-BN scale, all steps
__device__ float g_c1[TT * CH];         // input-BN shift, all steps
__device__ int   g_done1[TT];           // fused1 completion counters
__device__ float g_h2all[(size_t)TT * NN * HH];   // bns(elu(gcn1)) for all t
__device__ float g_dvall[(size_t)TT * NN * HH];   // gcn2 output (dv) for all t

// ---------------- preprocessing (exactly 5 launches) ----------------------
__global__ void k_pre0(const float* __restrict__ bg, const float* __restrict__ bb,
                       const float* __restrict__ bm, const float* __restrict__ bv,
                       const float* __restrict__ lw,
                       const float* __restrict__ g1, const float* __restrict__ b1,
                       const float* __restrict__ m1, const float* __restrict__ v1) {
    int i = blockIdx.x * blockDim.x + threadIdx.x;
    if (i < NN) { g_deg[i] = 0; g_cnt[i] = 0; }   // MUST reset every call
    if (i < TT) g_done1[i] = 0;                   // MUST reset every call
    if (i < TT * CH) {
        float s = g1[i] * rsqrtf(v1[i] + EPS_BN);
        g_s1[i] = s;
        g_c1[i] = b1[i] - m1[i] * s;
    }
    if (i < HH) {
        float s = bg[i] * rsqrtf(bv[i] + EPS_BN);
        g_ss[i] = s;
        g_cs[i] = bb[i] - bm[i] * s;
        float acc = 0.f;
        for (int o = 0; o < HH; o++) acc += lw[o * HH + i];
        g_lwsum[i] = acc;
    }
}

__global__ void k_deg(const int* __restrict__ ei) {
    int e = blockIdx.x * blockDim.x + threadIdx.x;
    if (e < EE) atomicAdd(&g_deg[ei[EE + e]], 1);
}

__global__ void k_scan_dinv() {
    __shared__ int buf[1024];
    __shared__ int carry;
    int tid = threadIdx.x;
    if (tid == 0) carry = 0;
    __syncthreads();
    for (int base = 0; base < NN; base += 1024) {
        int i = base + tid;
        int val = 0;
        if (i < NN) {
            val = g_deg[i];
            float d = (float)(val + 1);
            g_dinv[i]  = rsqrtf(d);
            g_snorm[i] = 1.0f / d;
        }
        buf[tid] = val;
        __syncthreads();
        for (int off = 1; off < 1024; off <<= 1) {
            int t2 = (tid >= off) ? buf[tid - off] : 0;
            __syncthreads();
            buf[tid] += t2;
            __syncthreads();
        }
        if (i < NN) g_off[i] = carry + buf[tid] - val;   // exclusive
        __syncthreads();
        if (tid == 0) carry += buf[1023];
        __syncthreads();
    }
    if (tid == 0) g_off[NN] = carry;
}

__global__ void k_fill(const int* __restrict__ ei) {
    int e = blockIdx.x * blockDim.x + threadIdx.x;
    if (e < EE) {
        int s = ei[e];
        int d = ei[EE + e];
        int pos = g_off[d] + atomicAdd(&g_cnt[d], 1);
        g_epack[pos] = make_int2(s, __float_as_int(g_dinv[s] * g_dinv[d]));
    }
}

__global__ void k_rsum() {
    int n = blockIdx.x * blockDim.x + threadIdx.x;
    if (n < NN) {
        float r = g_snorm[n];
        int e1 = g_off[n + 1];
        for (int e = g_off[n]; e < e1; e++) r += __int_as_float(g_epack[e].y);
        g_rsum[n] = r;
    }
}

// ---------------- role bodies (round-11 proven versions) ------------------
// step1: agg(x chunk t)+BN fold -> GEMM1(64->96) -> elu -> bns -> h2all[t]
__device__ __forceinline__ void body1(
    float* dsm, int bx, int t,
    const float* __restrict__ x, const float* __restrict__ w1,
    const float* __restrict__ b1)
{
    float* a_s = dsm;                 // [64][68]
    float* w_s = dsm + CH * 68;       // [64][96]

    int tid  = threadIdx.x;
    int warp = tid >> 5;
    int lane = tid & 31;
    int m0   = bx * 64;

    const float* wt = w1 + t * CH * HH;
    for (int idx = tid; idx < CH * HH; idx += 384)
        w_s[idx] = wt[idx];

    const float* s1 = g_s1 + t * CH;
    const float* c1 = g_c1 + t * CH;
    float s1a = s1[2 * lane], s1b = s1[2 * lane + 1];
    float c1a = c1[2 * lane], c1b = c1[2 * lane + 1];
    for (int m = warp; m < 64; m += 12) {
        int n = m0 + m;
        if (n >= NN) { a_s[(2 * lane) * 68 + m] = 0.f; a_s[(2 * lane + 1) * 68 + m] = 0.f; continue; }
        const float2* xb = (const float2*)(x + (size_t)n * CIN + t * CH);
        float sn = g_snorm[n];
        float2 xv = xb[lane];
        float a0 = sn * xv.x;
        float a1 = sn * xv.y;
        int e0 = g_off[n], e1 = g_off[n + 1];
#pragma unroll 4
        for (int e = e0; e < e1; e++) {
            int2  p = g_epack[e];
            float w = __int_as_float(p.y);
            float2 v = ((const float2*)(x + (size_t)p.x * CIN + t * CH))[lane];
            a0 += w * v.x;
            a1 += w * v.y;
        }
        float r = g_rsum[n];
        a_s[(2 * lane) * 68 + m]     = a0 * s1a + r * c1a;
        a_s[(2 * lane + 1) * 68 + m] = a1 * s1b + r * c1b;
    }
    __syncthreads();

    int mt = (tid & 15) * 4;   // 0..60
    int jt = (tid >> 4) * 4;   // 0..92
    float acc[4][4] = {};
#pragma unroll 8
    for (int k = 0; k < CH; k++) {
        float4 av = *(const float4*)&a_s[k * 68 + mt];
        float4 wv = *(const float4*)&w_s[k * HH + jt];
        acc[0][0] += av.x * wv.x; acc[0][1] += av.x * wv.y; acc[0][2] += av.x * wv.z; acc[0][3] += av.x * wv.w;
        acc[1][0] += av.y * wv.x; acc[1][1] += av.y * wv.y; acc[1][2] += av.y * wv.z; acc[1][3] += av.y * wv.w;
        acc[2][0] += av.z * wv.x; acc[2][1] += av.z * wv.y; acc[2][2] += av.z * wv.z; acc[2][3] += av.z * wv.w;
        acc[3][0] += av.w * wv.x; acc[3][1] += av.w * wv.y; acc[3][2] += av.w * wv.z; acc[3][3] += av.w * wv.w;
    }

    const float* b1t = b1 + t * HH;
    float bj[4], ssj[4], csj[4];
#pragma unroll
    for (int j = 0; j < 4; j++) {
        bj[j]  = b1t[jt + j];
        ssj[j] = g_ss[jt + j];
        csj[j] = g_cs[jt + j];
    }
    float* h2 = g_h2all + (size_t)t * NN * HH;
#pragma unroll
    for (int i = 0; i < 4; i++) {
        int n = m0 + mt + i;
        if (n < NN) {
            float o[4];
#pragma unroll
            for (int j = 0; j < 4; j++) {
                float z = acc[i][j] + bj[j];
                z = (z > 0.f) ? z : expm1f(z);
                o[j] = z * ssj[j] + csj[j];
            }
            *(float4*)&h2[(size_t)n * HH + jt] = make_float4(o[0], o[1], o[2], o[3]);
        }
    }
    // release: all writes of this block done -> bump counter
    __syncthreads();
    if (tid == 0) {
        __threadfence();
        atomicAdd(&g_done1[t], 1);
    }
}

// step2: agg(h2all[t]) -> GEMM2(96->96)+b2 -> dvall[t]
__device__ __forceinline__ void body2(
    float* dsm, int bx, int t,
    const float* __restrict__ w2, const float* __restrict__ b2)
{
    float* a_s = dsm;                    // [96][68]
    float* w_s = dsm + HH * 68;          // [96][96]

    int tid  = threadIdx.x;
    int warp = tid >> 5;
    int lane = tid & 31;
    int m0   = bx * 64;

    // acquire: wait until all NB producer blocks for this t are done
    if (tid == 0) {
        int v;
        const int* ctr = &g_done1[t];
        do {
            asm volatile("ld.acquire.gpu.u32 %0, [%1];" : "=r"(v) : "l"(ctr));
            if (v < NB) __nanosleep(200);
        } while (v < NB);
    }
    __syncthreads();

    for (int idx = tid; idx < HH * HH; idx += 384)
        w_s[idx] = w2[idx];

    const float* h2 = g_h2all + (size_t)t * NN * HH;
    for (int m = warp; m < 64; m += 12) {
        int n = m0 + m;
        if (n >= NN) {
            a_s[(2 * lane) * 68 + m]     = 0.f;
            a_s[(2 * lane + 1) * 68 + m] = 0.f;
            a_s[(64 + lane) * 68 + m]    = 0.f;
            continue;
        }
        const float* hb = h2 + (size_t)n * HH;
        float sn = g_snorm[n];
        float2 hv = ((const float2*)hb)[lane];
        float a0 = sn * hv.x;
        float a1 = sn * hv.y;
        float a2 = sn * hb[64 + lane];
        int e0 = g_off[n], e1 = g_off[n + 1];
#pragma unroll 4
        for (int e = e0; e < e1; e++) {
            int2  p = g_epack[e];
            float w = __int_as_float(p.y);
            const float* hs = h2 + (size_t)p.x * HH;
            float2 v = ((const float2*)hs)[lane];
            a0 += w * v.x;
            a1 += w * v.y;
            a2 += w * hs[64 + lane];
        }
        a_s[(2 * lane) * 68 + m]     = a0;
        a_s[(2 * lane + 1) * 68 + m] = a1;
        a_s[(64 + lane) * 68 + m]    = a2;
    }
    __syncthreads();

    int mt = (tid & 15) * 4;
    int jt = (tid >> 4) * 4;
    float acc[4][4] = {};
#pragma unroll 8
    for (int k = 0; k < HH; k++) {
        float4 av = *(const float4*)&a_s[k * 68 + mt];
        float4 wv = *(const float4*)&w_s[k * HH + jt];
        acc[0][0] += av.x * wv.x; acc[0][1] += av.x * wv.y; acc[0][2] += av.x * wv.z; acc[0][3] += av.x * wv.w;
        acc[1][0] += av.y * wv.x; acc[1][1] += av.y * wv.y; acc[1][2] += av.y * wv.z; acc[1][3] += av.y * wv.w;
        acc[2][0] += av.z * wv.x; acc[2][1] += av.z * wv.y; acc[2][2] += av.z * wv.z; acc[2][3] += av.z * wv.w;
        acc[3][0] += av.w * wv.x; acc[3][1] += av.w * wv.y; acc[3][2] += av.w * wv.z; acc[3][3] += av.w * wv.w;
    }

    float bj[4];
#pragma unroll
    for (int j = 0; j < 4; j++) bj[j] = b2[jt + j];

    float* dv = g_dvall + (size_t)t * NN * HH;
#pragma unroll
    for (int i = 0; i < 4; i++) {
        int n = m0 + mt + i;
        if (n < NN) {
            *(float4*)&dv[(size_t)n * HH + jt] =
                make_float4(acc[i][0] + bj[0], acc[i][1] + bj[1],
                            acc[i][2] + bj[2], acc[i][3] + bj[3]);
        }
    }
}

// ---------------- merged heterogeneous launch -----------------------------
// 1D grid of 64*NB blocks; chunk order interleaves producers and consumers:
//   c=0: f1(0)   c=1: f1(1)
//   c=2+2i: f2(i), c=3+2i: f1(i+2)   for i=0..29
//   c=62: f2(30), c=63: f2(31)
// Consumers always dispatch AFTER all their producers (in-order CTA queue),
// so the acquire spin is short and deadlock-free.
#define SMEM_BYTES ((HH * 68 + HH * HH) * 4)
__global__ __launch_bounds__(384) void k_all(
    const float* __restrict__ x, const float* __restrict__ w1,
    const float* __restrict__ b1, const float* __restrict__ w2,
    const float* __restrict__ b2)
{
    extern __shared__ float dsm[];
    int c  = blockIdx.x / NB;
    int bx = blockIdx.x - c * NB;

    int role, t;
    if (c < 2)            { role = 1; t = c; }
    else if (c >= 62)     { role = 2; t = c - 32; }
    else if ((c & 1) == 0){ role = 2; t = (c - 2) >> 1; }
    else                  { role = 1; t = ((c - 3) >> 1) + 2; }

    if (role == 1) body1(dsm, bx, t, x, w1, b1);
    else           body2(dsm, bx, t, w2, b2);
}

// ---------------- PLIF scan: one warp per node, loop over t ---------------
__global__ __launch_bounds__(256) void k_plif(const float* __restrict__ tau,
                                              float* __restrict__ out)
{
    int gw   = (blockIdx.x * blockDim.x + threadIdx.x) >> 5;
    int lane = threadIdx.x & 31;
    if (gw >= NN) return;

    float l0 = g_lwsum[lane];
    float l1 = g_lwsum[lane + 32];
    float l2 = g_lwsum[lane + 64];
    float tauv = *tau;
    float rtau = 1.0f / tauv;

    float v0 = 0.f, v1 = 0.f, v2 = 0.f;
    size_t base = (size_t)gw * HH;
#pragma unroll 4
    for (int t = 0; t < TT; t++) {
        const float* dvp = g_dvall + (size_t)t * NN * HH + base;
        float d0 = dvp[lane];
        float d1 = dvp[lane + 32];
        float d2 = dvp[lane + 64];
        float n0 = v0 + (d0 - v0) * rtau;
        float n1 = v1 + (d1 - v1) * rtau;
        float n2 = v2 + (d2 - v2) * rtau;
        bool s0 = (n0 - VTH) > 0.f;
        bool s1 = (n1 - VTH) > 0.f;
        bool s2 = (n2 - VTH) > 0.f;
        v0 = s0 ? 0.f : n0;
        v1 = s1 ? 0.f : n1;
        v2 = s2 ? 0.f : n2;
        float pl = (s0 ? l0 : 0.f) + (s1 ? l1 : 0.f) + (s2 ? l2 : 0.f);
#pragma unroll
        for (int off = 16; off > 0; off >>= 1)
            pl += __shfl_down_sync(0xffffffff, pl, off);
        if (lane == 0) out[t * NN + gw] = pl;
    }
}

// ---------------- launch --------------------------------------------------
extern "C" void kernel_launch(void* const* d_in, const int* in_sizes, int n_in,
                              void* d_out, int out_size) {
    const float* x      = (const float*)d_in[0];
    const int*   ei     = (const int*)  d_in[1];
    const float* w1     = (const float*)d_in[2];
    const float* b1     = (const float*)d_in[3];
    const float* bn1_g  = (const float*)d_in[4];
    const float* bn1_b  = (const float*)d_in[5];
    const float* bn1_m  = (const float*)d_in[6];
    const float* bn1_v  = (const float*)d_in[7];
    const float* bns_g  = (const float*)d_in[8];
    const float* bns_b  = (const float*)d_in[9];
    const float* bns_m  = (const float*)d_in[10];
    const float* bns_v  = (const float*)d_in[11];
    const float* w2     = (const float*)d_in[12];
    const float* b2     = (const float*)d_in[13];
    const float* lin_w  = (const float*)d_in[14];
    const float* tau    = (const float*)d_in[15];
    float* out = (float*)d_out;

    static bool attr_set = false;
    if (!attr_set) {
        cudaFuncSetAttribute(k_all, cudaFuncAttributeMaxDynamicSharedMemorySize, SMEM_BYTES);
        attr_set = true;
    }

    // exactly 5 preprocessing launches (grids cover the state they must reset!)
    k_pre0<<<(NN + 255) / 256, 256>>>(bns_g, bns_b, bns_m, bns_v, lin_w,
                                      bn1_g, bn1_b, bn1_m, bn1_v);
    k_deg<<<(EE + 255) / 256, 256>>>(ei);
    k_scan_dinv<<<1, 1024>>>();
    k_fill<<<(EE + 255) / 256, 256>>>(ei);
    k_rsum<<<(NN + 255) / 256, 256>>>();

    // 2 hot launches: merged producer/consumer pipeline, then PLIF scan
    k_all<<<64 * NB, 384, SMEM_BYTES>>>(x, w1, b1, w2, b2);
    k_plif<<<(NN * 32 + 255) / 256, 256>>>(tau, out);
}